// round 16
// baseline (speedup 1.0000x reference)
#include <cuda_runtime.h>
#include <cuda_bf16.h>

// Problem constants (fixed by reference)
#define BATCH   2
#define SEQ     512
#define DMODEL  512
#define NHEADS  8
#define DK      64
#define BL      (BATCH*SEQ)   // 1024 rows
#define HALF    (BL*DMODEL)   // one buffer (floats)

// ---------------- scratch (device globals; no allocation allowed) ----------
__device__ float g_WqE[DMODEL*DMODEL];
__device__ float g_WkE[DMODEL*DMODEL];
__device__ float g_bqE[DMODEL];
__device__ float g_bkE[DMODEL];
__device__ float g_qp[HALF];
__device__ float g_kp[HALF];
__device__ float g_V [HALF];
__device__ float g_att[HALF];
__device__ float g_wp[2*HALF];   // Wo split-K partials

__device__ __forceinline__ float tanh_fast(float x) {
    float y;
    asm("tanh.approx.f32 %0, %1;" : "=f"(y) : "f"(x));
    return y;
}

// ---------------------------------------------------------------------------
// Prep: effective weights via tiled mini-GEMMs (coalesced).
// ---------------------------------------------------------------------------
__global__ __launch_bounds__(256) void prep_eff(
    const float* __restrict__ Wq, const float* __restrict__ Aq,
    const float* __restrict__ Wk, const float* __restrict__ Ak,
    const float* __restrict__ bq, const float* __restrict__ bk) {
    __shared__ float Ws[64*68];   // Ws[d][ii]
    __shared__ float At[64*68];   // At[d][dp]
    int t   = threadIdx.x;
    int it  = blockIdx.x;
    int h   = blockIdx.y;
    int sel = blockIdx.z;
    const float* W = sel ? Wk : Wq;
    const float* A = sel ? Ak : Aq;
    float* WE = sel ? g_WkE : g_WqE;
    const float* bsrc = sel ? bk : bq;
    float* bE = sel ? g_bkE : g_bqE;

    for (int idx = t; idx < 64*64; idx += 256) {
        int d = idx >> 6, ii = idx & 63;
        Ws[d*68 + ii] = W[(h*64 + d)*DMODEL + it*64 + ii];
    }
    for (int idx = t; idx < 64*64; idx += 256) {
        int dp = idx >> 6, d = idx & 63;
        At[d*68 + dp] = A[dp*64 + d];
    }
    __syncthreads();

    int tx = t & 15, ty = t >> 4;
    int dp4 = tx * 4, ii4 = ty * 4;
    float acc[4][4];
#pragma unroll
    for (int i = 0; i < 4; i++)
#pragma unroll
        for (int j = 0; j < 4; j++) acc[i][j] = 0.f;

#pragma unroll 8
    for (int d = 0; d < 64; d++) {
        float4 a4 = *(const float4*)&Ws[d*68 + ii4];
        float4 b4 = *(const float4*)&At[d*68 + dp4];
        float aa[4] = {a4.x, a4.y, a4.z, a4.w};
        float bb[4] = {b4.x, b4.y, b4.z, b4.w};
#pragma unroll
        for (int i = 0; i < 4; i++)
#pragma unroll
            for (int j = 0; j < 4; j++)
                acc[i][j] += aa[i] * bb[j];
    }
#pragma unroll
    for (int i = 0; i < 4; i++) {
        int row = it*64 + ii4 + i;
        *(float4*)&WE[row*DMODEL + h*64 + dp4] =
            make_float4(acc[i][0], acc[i][1], acc[i][2], acc[i][3]);
    }
    if (it == 0 && t < 64) {
        float s = 0.f;
#pragma unroll 8
        for (int d = 0; d < 64; d++)
            s += bsrc[h*64 + d] * At[d*68 + t];
        bE[h*64 + t] = s;
    }
}

// ---------------------------------------------------------------------------
// GEMM 64x64 (optional split-K, optional bias): M=1024, N=K=512.
// ---------------------------------------------------------------------------
__global__ __launch_bounds__(256) void gemm64(
    const float* __restrict__ A0, const float* __restrict__ B0, int t0,
    const float* __restrict__ c0, float* __restrict__ C0,
    const float* __restrict__ A1, const float* __restrict__ B1, int t1,
    const float* __restrict__ c1, float* __restrict__ C1,
    const float* __restrict__ A2, const float* __restrict__ B2, int t2,
    const float* __restrict__ c2, float* __restrict__ C2,
    int nsplit, int KS) {
    const int K = DMODEL, N = DMODEL;
    int z = blockIdx.z;
    int g = z / nsplit, part = z - g * nsplit;
    const float* A    = (g == 0) ? A0 : (g == 1) ? A1 : A2;
    const float* Bm   = (g == 0) ? B0 : (g == 1) ? B1 : B2;
    int tb            = (g == 0) ? t0 : (g == 1) ? t1 : t2;
    const float* bias = (g == 0) ? c0 : (g == 1) ? c1 : c2;
    float* C          = ((g == 0) ? C0 : (g == 1) ? C1 : C2) + part * HALF;
    int kbase = part * KS;

    __shared__ float As[2][16*68];
    __shared__ float Bs[2][16*68];

    int t  = threadIdx.x;          // 256
    int bm = blockIdx.y * 64;
    int bn = blockIdx.x * 64;
    int tx = t & 15, ty = t >> 4;

    float acc[4][4];
#pragma unroll
    for (int i = 0; i < 4; i++)
#pragma unroll
        for (int j = 0; j < 4; j++) acc[i][j] = 0.f;

    int arow = t >> 2, akc = (t & 3) << 2;
    int bkr = t >> 4, bnc = (t & 15) << 2;

    float4 ra, rb;
    auto fetch = [&](int k0) {
        ra = *(const float4*)(A + (bm + arow)*K + k0 + akc);
        if (tb == 0)
            rb = *(const float4*)(Bm + (k0 + bkr)*N + bn + bnc);
        else
            rb = *(const float4*)(Bm + (bn + arow)*K + k0 + akc);
    };
    auto stage = [&](int buf) {
        As[buf][(akc+0)*68 + arow] = ra.x;
        As[buf][(akc+1)*68 + arow] = ra.y;
        As[buf][(akc+2)*68 + arow] = ra.z;
        As[buf][(akc+3)*68 + arow] = ra.w;
        if (tb == 0) {
            *(float4*)&Bs[buf][bkr*68 + bnc] = rb;
        } else {
            Bs[buf][(akc+0)*68 + arow] = rb.x;
            Bs[buf][(akc+1)*68 + arow] = rb.y;
            Bs[buf][(akc+2)*68 + arow] = rb.z;
            Bs[buf][(akc+3)*68 + arow] = rb.w;
        }
    };

    fetch(kbase);
    stage(0);
    int cur = 0;
    int kend = kbase + KS;
    for (int k0 = kbase; k0 < kend; k0 += 16) {
        __syncthreads();
        bool more = (k0 + 16) < kend;
        if (more) fetch(k0 + 16);
#pragma unroll
        for (int k = 0; k < 16; k++) {
            float4 a4 = *(const float4*)&As[cur][k*68 + ty*4];
            float4 b4 = *(const float4*)&Bs[cur][k*68 + tx*4];
            float aa[4] = {a4.x, a4.y, a4.z, a4.w};
            float bb[4] = {b4.x, b4.y, b4.z, b4.w};
#pragma unroll
            for (int i = 0; i < 4; i++)
#pragma unroll
                for (int j = 0; j < 4; j++)
                    acc[i][j] += aa[i] * bb[j];
        }
        if (more) stage(cur ^ 1);
        cur ^= 1;
    }

    float4 bvec = make_float4(0.f, 0.f, 0.f, 0.f);
    if (bias) bvec = *(const float4*)(bias + bn + tx*4);
#pragma unroll
    for (int i = 0; i < 4; i++) {
        int row = bm + ty*4 + i;
        float4 o;
        o.x = acc[i][0] + bvec.x;
        o.y = acc[i][1] + bvec.y;
        o.z = acc[i][2] + bvec.z;
        o.w = acc[i][3] + bvec.w;
        *(float4*)&C[row*N + bn + tx*4] = o;
    }
}

// ---------------------------------------------------------------------------
// Reduce Wo partials: out = wp0 + wp1 + bo
// ---------------------------------------------------------------------------
__global__ __launch_bounds__(256) void reduce_out(
    float* __restrict__ out, const float* __restrict__ bo) {
    int f = blockIdx.x * blockDim.x + threadIdx.x;
    float4 a = *(const float4*)(g_wp + f*4);
    float4 b = *(const float4*)(g_wp + HALF + f*4);
    float4 bb = *(const float4*)(bo + (f & 127)*4);
    float4 o;
    o.x = a.x + b.x + bb.x;
    o.y = a.y + b.y + bb.y;
    o.z = a.z + b.z + bb.z;
    o.w = a.w + b.w + bb.w;
    *(float4*)(out + f*4) = o;
}

// ---------------------------------------------------------------------------
// Attention v4c — warp-group phase stagger, REGISTER-RELIEVED.
// Identical structure to v4b (race-fixed), but __launch_bounds__(256) with
// min-blocks 1: ptxas may use up to 255 regs/thread, enabling deep LDS/MUFU
// software pipelining in the A-phase chunks (previously capped at 128 regs,
// starving the MUFU port). Occupancy drops to 1 CTA/SM; MUFU-work makespan
// is unchanged (2 waves x ~34us/CTA == 2 co-resident CTAs' serialized work).
// ---------------------------------------------------------------------------
#define SKO  0
#define SVO  (64*68)                 // 2 buffers
#define SPO  (SVO + 2*64*68)         // 2 buffers
#define AVO  (SPO + 2*32*65)
#define PRTO (AVO + 64)
#define INVO (PRTO + 256)
#define ATTN_SMEM ((INVO + 32) * 4)

__global__ __launch_bounds__(256) void attn_kernel(
    const float* __restrict__ qp, const float* __restrict__ kp,
    const float* __restrict__ V,  const float* __restrict__ av,
    float* __restrict__ out) {
    extern __shared__ float sm[];
    float* sk     = sm + SKO;
    float* sv     = sm + SVO;
    float* sp     = sm + SPO;
    float* s_av   = sm + AVO;
    float* s_part = sm + PRTO;
    float* s_inv  = sm + INVO;

    int t    = threadIdx.x;         // 256
    int lane = t & 31;
    int wid  = t >> 5;
    int i0   = blockIdx.x * 32;
    int bh   = blockIdx.y;
    int b    = bh >> 3, h = bh & 7;
    const int h64 = h * 64;
    const int rowbase = b * SEQ;

    if (t < 64) s_av[t] = av[t];

    // this thread's query row (query = lane) in registers
    float q_r[64];
    {
        const float* qrow = qp + (rowbase + i0 + lane) * DMODEL + h64;
#pragma unroll
        for (int d = 0; d < 64; d += 4) {
            float4 v4 = *(const float4*)(qrow + d);
            q_r[d] = v4.x; q_r[d+1] = v4.y; q_r[d+2] = v4.z; q_r[d+3] = v4.w;
        }
    }

    // phase-B mapping: thread owns 2 queries x 4 d
    int dt = t & 15, ig = t >> 4;
    int d4 = dt << 2;
    int ia = ig << 1;
    float acc0[4] = {0.f, 0.f, 0.f, 0.f};
    float acc1[4] = {0.f, 0.f, 0.f, 0.f};
    float psum = 0.f;

    int frow = t >> 2;
    int fc16 = (t & 3) << 4;
    bool groupX = (wid < 4);        // A-first group

    __syncthreads();                // s_av visible

#pragma unroll 1
    for (int n = 0; n <= 8; n++) {
        if (n < 8) {
            int jt = n * 64;
            const float* ks = kp + (rowbase + jt + frow) * DMODEL + h64 + fc16;
            const float* vs = V  + (rowbase + jt + frow) * DMODEL + h64 + fc16;
            float4 k0 = *(const float4*)(ks + 0);
            float4 k1 = *(const float4*)(ks + 4);
            float4 k2 = *(const float4*)(ks + 8);
            float4 k3 = *(const float4*)(ks + 12);
            float4 v0 = *(const float4*)(vs + 0);
            float4 v1 = *(const float4*)(vs + 4);
            float4 v2 = *(const float4*)(vs + 8);
            float4 v3 = *(const float4*)(vs + 12);
            float* dk = &sk[frow*68 + fc16];
            float* dv = &sv[(n & 1)*64*68 + frow*68 + fc16];
            *(float4*)(dk + 0)  = k0;
            *(float4*)(dk + 4)  = k1;
            *(float4*)(dk + 8)  = k2;
            *(float4*)(dk + 12) = k3;
            *(float4*)(dv + 0)  = v0;
            *(float4*)(dv + 4)  = v1;
            *(float4*)(dv + 8)  = v2;
            *(float4*)(dv + 12) = v3;
        }
        __syncthreads();            // staging visible; prev phases complete

#pragma unroll 1
        for (int ph = 0; ph < 2; ph++) {
            bool aslot = ((ph == 0) == groupX);
            if (aslot) {
                if (n < 8) {
                    // ---- phase A: scores -> p = exp(s) -> sp[n&1] ----
                    float* spc = &sp[(n & 1)*32*65];
#pragma unroll
                    for (int jj = 0; jj < 8; jj++) {
                        int j = wid * 8 + jj;       // warp-uniform -> broadcast
                        const float* krow = &sk[j*68];
                        float s = 0.f;
#pragma unroll
                        for (int d = 0; d < 64; d += 4) {
                            float4 k4 = *(const float4*)(krow + d);
                            float4 a4 = *(const float4*)(&s_av[d]);
                            s += a4.x * tanh_fast(q_r[d+0] + k4.x);
                            s += a4.y * tanh_fast(q_r[d+1] + k4.y);
                            s += a4.z * tanh_fast(q_r[d+2] + k4.z);
                            s += a4.w * tanh_fast(q_r[d+3] + k4.w);
                        }
                        float p = __expf(s);        // |s| <= sum|av| ~ 10: safe
                        spc[lane*65 + j] = p;
                        psum += p;
                    }
                }
            } else {
                if (n > 0) {
                    // ---- phase B: acc += P(n-1) @ V(n-1) ----
                    const float* spp = &sp[((n-1) & 1)*32*65];
                    const float* svp = &sv[((n-1) & 1)*64*68];
                    const float* p0 = &spp[ia*65];
                    const float* p1 = &spp[(ia+1)*65];
#pragma unroll 8
                    for (int j = 0; j < 64; j++) {
                        float4 v = *(const float4*)&svp[j*68 + d4];
                        float pa = p0[j];
                        float pb = p1[j];
                        acc0[0] += pa * v.x; acc0[1] += pa * v.y;
                        acc0[2] += pa * v.z; acc0[3] += pa * v.w;
                        acc1[0] += pb * v.x; acc1[1] += pb * v.y;
                        acc1[2] += pb * v.z; acc1[3] += pb * v.w;
                    }
                }
            }
        }
        __syncthreads();            // all reads of sk/sv/sp done before
                                    // next iteration's staging
    }

    // ---- finalize softmax sums ----
    s_part[wid*32 + lane] = psum;
    __syncthreads();
    if (t < 32) {
        float ssum = 0.f;
#pragma unroll
        for (int w = 0; w < 8; w++) ssum += s_part[w*32 + t];
        s_inv[t] = 1.f / ssum;
    }
    __syncthreads();

    float s0 = s_inv[ia], s1 = s_inv[ia+1];
    float4 o0, o1;
    o0.x = acc0[0]*s0; o0.y = acc0[1]*s0; o0.z = acc0[2]*s0; o0.w = acc0[3]*s0;
    o1.x = acc1[0]*s1; o1.y = acc1[1]*s1; o1.z = acc1[2]*s1; o1.w = acc1[3]*s1;
    *(float4*)&out[(rowbase + i0 + ia    ) * DMODEL + h64 + d4] = o0;
    *(float4*)&out[(rowbase + i0 + ia + 1) * DMODEL + h64 + d4] = o1;
}

// ---------------------------------------------------------------------------
extern "C" void kernel_launch(void* const* d_in, const int* in_sizes, int n_in,
                              void* d_out, int out_size) {
    const float* query = (const float*)d_in[0];
    const float* key   = (const float*)d_in[1];
    const float* value = (const float*)d_in[2];
    const float* Wq    = (const float*)d_in[3];
    const float* bq    = (const float*)d_in[4];
    const float* Wk    = (const float*)d_in[5];
    const float* bk    = (const float*)d_in[6];
    const float* Wv    = (const float*)d_in[7];
    const float* bv    = (const float*)d_in[8];
    const float* Wo    = (const float*)d_in[9];
    const float* bo    = (const float*)d_in[10];
    const float* Aq    = (const float*)d_in[11];
    const float* Ak    = (const float*)d_in[12];
    const float* av    = (const float*)d_in[13];
    float* out = (float*)d_out;

    float *pWqE, *pWkE, *pbqE, *pbkE, *pqp, *pkp, *pV, *patt, *pwp;
    cudaGetSymbolAddress((void**)&pWqE, g_WqE);
    cudaGetSymbolAddress((void**)&pWkE, g_WkE);
    cudaGetSymbolAddress((void**)&pbqE, g_bqE);
    cudaGetSymbolAddress((void**)&pbkE, g_bkE);
    cudaGetSymbolAddress((void**)&pqp,  g_qp);
    cudaGetSymbolAddress((void**)&pkp,  g_kp);
    cudaGetSymbolAddress((void**)&pV,   g_V);
    cudaGetSymbolAddress((void**)&patt, g_att);
    cudaGetSymbolAddress((void**)&pwp,  g_wp);

    cudaFuncSetAttribute(attn_kernel, cudaFuncAttributeMaxDynamicSharedMemorySize, ATTN_SMEM);

    // prep: effective Q/K weights + biases
    prep_eff<<<dim3(8, 8, 2), 256>>>(Wq, Aq, Wk, Ak, bq, bk);

    // Q/K/V projection GEMMs: no split-K, bias in epilogue -> 384 CTAs
    gemm64<<<dim3(8, 16, 3), 256>>>(query, pWqE, 0, pbqE, pqp,
                                    key,   pWkE, 0, pbkE, pkp,
                                    value, Wv,   1, bv,   pV,
                                    1, 512);

    // attention (warp-staggered, register-relieved) -> 256 CTAs
    attn_kernel<<<dim3(SEQ/32, BATCH*NHEADS), 256, ATTN_SMEM>>>(pqp, pkp, pV, av, patt);

    // output projection, split-K x2 -> 256 CTAs
    gemm64<<<dim3(8, 16, 2), 256>>>(patt, Wo, 1, nullptr, pwp,
                                    patt, Wo, 1, nullptr, pwp,
                                    patt, Wo, 1, nullptr, pwp,
                                    2, 256);
    reduce_out<<<(HALF/4)/256, 256>>>(out, bo);
}

// round 17
// speedup vs baseline: 1.1199x; 1.1199x over previous
#include <cuda_runtime.h>
#include <cuda_bf16.h>

// Problem constants (fixed by reference)
#define BATCH   2
#define SEQ     512
#define DMODEL  512
#define NHEADS  8
#define DK      64
#define BL      (BATCH*SEQ)   // 1024 rows
#define HALF    (BL*DMODEL)   // one buffer (floats)

// ---------------- scratch (device globals; no allocation allowed) ----------
__device__ float g_WqE[DMODEL*DMODEL];
__device__ float g_WkE[DMODEL*DMODEL];
__device__ float g_bqE[DMODEL];
__device__ float g_bkE[DMODEL];
__device__ float g_qp[HALF];
__device__ float g_kp[HALF];
__device__ float g_V [HALF];
__device__ float g_att[HALF];
__device__ float g_wp[4*HALF];   // Wo split-K partials

__device__ __forceinline__ float tanh_fast(float x) {
    float y;
    asm("tanh.approx.f32 %0, %1;" : "=f"(y) : "f"(x));
    return y;
}
__device__ __forceinline__ unsigned cvt_tf32(float x) {
    unsigned r;
    asm("cvt.rna.tf32.f32 %0, %1;" : "=r"(r) : "f"(x));
    return r;
}

// ---------------------------------------------------------------------------
// Prep: effective weights via tiled mini-GEMMs (coalesced, FFMA — tiny).
// ---------------------------------------------------------------------------
__global__ __launch_bounds__(256) void prep_eff(
    const float* __restrict__ Wq, const float* __restrict__ Aq,
    const float* __restrict__ Wk, const float* __restrict__ Ak,
    const float* __restrict__ bq, const float* __restrict__ bk) {
    __shared__ float Ws[64*68];   // Ws[d][ii]
    __shared__ float At[64*68];   // At[d][dp]
    int t   = threadIdx.x;
    int it  = blockIdx.x;
    int h   = blockIdx.y;
    int sel = blockIdx.z;
    const float* W = sel ? Wk : Wq;
    const float* A = sel ? Ak : Aq;
    float* WE = sel ? g_WkE : g_WqE;
    const float* bsrc = sel ? bk : bq;
    float* bE = sel ? g_bkE : g_bqE;

    for (int idx = t; idx < 64*64; idx += 256) {
        int d = idx >> 6, ii = idx & 63;
        Ws[d*68 + ii] = W[(h*64 + d)*DMODEL + it*64 + ii];
    }
    for (int idx = t; idx < 64*64; idx += 256) {
        int dp = idx >> 6, d = idx & 63;
        At[d*68 + dp] = A[dp*64 + d];
    }
    __syncthreads();

    int tx = t & 15, ty = t >> 4;
    int dp4 = tx * 4, ii4 = ty * 4;
    float acc[4][4];
#pragma unroll
    for (int i = 0; i < 4; i++)
#pragma unroll
        for (int j = 0; j < 4; j++) acc[i][j] = 0.f;

#pragma unroll 8
    for (int d = 0; d < 64; d++) {
        float4 a4 = *(const float4*)&Ws[d*68 + ii4];
        float4 b4 = *(const float4*)&At[d*68 + dp4];
        float aa[4] = {a4.x, a4.y, a4.z, a4.w};
        float bb[4] = {b4.x, b4.y, b4.z, b4.w};
#pragma unroll
        for (int i = 0; i < 4; i++)
#pragma unroll
            for (int j = 0; j < 4; j++)
                acc[i][j] += aa[i] * bb[j];
    }
#pragma unroll
    for (int i = 0; i < 4; i++) {
        int row = it*64 + ii4 + i;
        *(float4*)&WE[row*DMODEL + h*64 + dp4] =
            make_float4(acc[i][0], acc[i][1], acc[i][2], acc[i][3]);
    }
    if (it == 0 && t < 64) {
        float s = 0.f;
#pragma unroll 8
        for (int d = 0; d < 64; d++)
            s += bsrc[h*64 + d] * At[d*68 + t];
        bE[h*64 + t] = s;
    }
}

// ---------------------------------------------------------------------------
// TF32 tensor-core GEMM: C[M,N] = A[M,K] @ B (+bias). M=1024, N=K=512.
// CTA tile 128x64, 256 threads = 8 warps (4 m x 2 n), warp tile 32x32.
// mma.sync.aligned.m16n8k8.row.col.f32.tf32.tf32.f32, K-step 16, dbl-buffered.
// tb: 0 -> B is [K][N];  1 -> B is [N][K] (read transposed).
// blockIdx.z: g = z/nsplit selects GEMM, part = z%nsplit selects K slice.
// If bias != null it is added (use only with nsplit==1).
// Fragment layout (canonical, g=lane>>2, t=lane&3):
//   A: a0=(g, t) a1=(g+8, t) a2=(g, t+4) a3=(g+8, t+4)   [row, k]
//   B: b0=(t, g) b1=(t+4, g)                              [k, n]
//   D: d0=(g, 2t) d1=(g, 2t+1) d2=(g+8, 2t) d3=(g+8, 2t+1)
// ---------------------------------------------------------------------------
__global__ __launch_bounds__(256) void gemm_tf32(
    const float* __restrict__ A0, const float* __restrict__ B0, int t0,
    const float* __restrict__ c0, float* __restrict__ C0,
    const float* __restrict__ A1, const float* __restrict__ B1, int t1,
    const float* __restrict__ c1, float* __restrict__ C1,
    const float* __restrict__ A2, const float* __restrict__ B2, int t2,
    const float* __restrict__ c2, float* __restrict__ C2,
    int nsplit, int KS) {
    const int K = DMODEL, N = DMODEL;
    int z = blockIdx.z;
    int g_ = z / nsplit, part = z - g_ * nsplit;
    const float* A    = (g_ == 0) ? A0 : (g_ == 1) ? A1 : A2;
    const float* Bm   = (g_ == 0) ? B0 : (g_ == 1) ? B1 : B2;
    int tb            = (g_ == 0) ? t0 : (g_ == 1) ? t1 : t2;
    const float* bias = (g_ == 0) ? c0 : (g_ == 1) ? c1 : c2;
    float* C          = ((g_ == 0) ? C0 : (g_ == 1) ? C1 : C2) + part * HALF;
    int kbase = part * KS;

    // As[k][row] (k-major for fragment gather), Bs[k][n]
    __shared__ unsigned As[2][16*132];
    __shared__ unsigned Bs[2][16*68];

    int t    = threadIdx.x;        // 256
    int lane = t & 31;
    int wid  = t >> 5;
    int bm   = blockIdx.y * 128;
    int bn   = blockIdx.x * 64;
    int wm   = (wid >> 1) * 32;    // warp m offset in tile
    int wn   = (wid & 1)  * 32;    // warp n offset in tile
    int gq   = lane >> 2;          // groupID 0..7
    int tg   = lane & 3;           // thread-in-group 0..3

    float acc[2][4][4];            // [mfrag][nfrag][reg]
#pragma unroll
    for (int mf = 0; mf < 2; mf++)
#pragma unroll
        for (int nf = 0; nf < 4; nf++)
#pragma unroll
            for (int r = 0; r < 4; r++) acc[mf][nf][r] = 0.f;

    // staging coords
    int a_row = (t*2) >> 2;        // thread loads A float4 pair: idx=t*2, t*2+1
    int b0_kr = t >> 4, b0_c4 = (t & 15) << 2;   // tb=0
    int b1_rw = t >> 2, b1_k4 = (t & 3) << 2;    // tb=1

    float4 ra[2], rb;
    auto fetch = [&](int k0) {
#pragma unroll
        for (int r = 0; r < 2; r++) {
            int idx = t*2 + r;
            ra[r] = *(const float4*)(A + (bm + (idx >> 2))*K + k0 + ((idx & 3) << 2));
        }
        if (tb == 0)
            rb = *(const float4*)(Bm + (k0 + b0_kr)*N + bn + b0_c4);
        else
            rb = *(const float4*)(Bm + (bn + b1_rw)*K + k0 + b1_k4);
    };
    auto stage = [&](int buf) {
#pragma unroll
        for (int r = 0; r < 2; r++) {
            int idx = t*2 + r;
            int row = idx >> 2, kc = (idx & 3) << 2;
            As[buf][(kc+0)*132 + row] = cvt_tf32(ra[r].x);
            As[buf][(kc+1)*132 + row] = cvt_tf32(ra[r].y);
            As[buf][(kc+2)*132 + row] = cvt_tf32(ra[r].z);
            As[buf][(kc+3)*132 + row] = cvt_tf32(ra[r].w);
        }
        if (tb == 0) {
            Bs[buf][b0_kr*68 + b0_c4+0] = cvt_tf32(rb.x);
            Bs[buf][b0_kr*68 + b0_c4+1] = cvt_tf32(rb.y);
            Bs[buf][b0_kr*68 + b0_c4+2] = cvt_tf32(rb.z);
            Bs[buf][b0_kr*68 + b0_c4+3] = cvt_tf32(rb.w);
        } else {
            Bs[buf][(b1_k4+0)*68 + b1_rw] = cvt_tf32(rb.x);
            Bs[buf][(b1_k4+1)*68 + b1_rw] = cvt_tf32(rb.y);
            Bs[buf][(b1_k4+2)*68 + b1_rw] = cvt_tf32(rb.z);
            Bs[buf][(b1_k4+3)*68 + b1_rw] = cvt_tf32(rb.w);
        }
    };

    fetch(kbase);
    stage(0);
    int cur = 0;
    int kend = kbase + KS;
    for (int k0 = kbase; k0 < kend; k0 += 16) {
        __syncthreads();
        bool more = (k0 + 16) < kend;
        if (more) fetch(k0 + 16);
        const unsigned* Ac = As[cur];
        const unsigned* Bc = Bs[cur];
#pragma unroll
        for (int h = 0; h < 2; h++) {      // two k8 halves
            int kl = h * 8;
            unsigned af[2][4], bf[4][2];
#pragma unroll
            for (int mf = 0; mf < 2; mf++) {
                int r0 = wm + mf*16;
                af[mf][0] = Ac[(kl+tg  )*132 + r0 + gq    ];
                af[mf][1] = Ac[(kl+tg  )*132 + r0 + gq + 8];
                af[mf][2] = Ac[(kl+tg+4)*132 + r0 + gq    ];
                af[mf][3] = Ac[(kl+tg+4)*132 + r0 + gq + 8];
            }
#pragma unroll
            for (int nf = 0; nf < 4; nf++) {
                int n0 = wn + nf*8;
                bf[nf][0] = Bc[(kl+tg  )*68 + n0 + gq];
                bf[nf][1] = Bc[(kl+tg+4)*68 + n0 + gq];
            }
#pragma unroll
            for (int mf = 0; mf < 2; mf++)
#pragma unroll
                for (int nf = 0; nf < 4; nf++) {
                    asm volatile(
                        "mma.sync.aligned.m16n8k8.row.col.f32.tf32.tf32.f32 "
                        "{%0,%1,%2,%3}, {%4,%5,%6,%7}, {%8,%9}, {%0,%1,%2,%3};"
                        : "+f"(acc[mf][nf][0]), "+f"(acc[mf][nf][1]),
                          "+f"(acc[mf][nf][2]), "+f"(acc[mf][nf][3])
                        : "r"(af[mf][0]), "r"(af[mf][1]),
                          "r"(af[mf][2]), "r"(af[mf][3]),
                          "r"(bf[nf][0]), "r"(bf[nf][1]));
                }
        }
        if (more) stage(cur ^ 1);
        cur ^= 1;
    }

    // epilogue
#pragma unroll
    for (int mf = 0; mf < 2; mf++) {
        int row0 = bm + wm + mf*16 + gq;
#pragma unroll
        for (int nf = 0; nf < 4; nf++) {
            int col = bn + wn + nf*8 + 2*tg;
            float bx = 0.f, by = 0.f;
            if (bias) { bx = bias[col]; by = bias[col+1]; }
            *(float2*)&C[row0*N + col] =
                make_float2(acc[mf][nf][0] + bx, acc[mf][nf][1] + by);
            *(float2*)&C[(row0+8)*N + col] =
                make_float2(acc[mf][nf][2] + bx, acc[mf][nf][3] + by);
        }
    }
}

// ---------------------------------------------------------------------------
// Reduce Wo partials: out = wp0+wp1+wp2+wp3 + bo
// ---------------------------------------------------------------------------
__global__ __launch_bounds__(256) void reduce_out(
    float* __restrict__ out, const float* __restrict__ bo) {
    int f = blockIdx.x * blockDim.x + threadIdx.x;
    float4 a = *(const float4*)(g_wp + f*4);
    float4 b = *(const float4*)(g_wp + HALF + f*4);
    float4 c = *(const float4*)(g_wp + 2*HALF + f*4);
    float4 d = *(const float4*)(g_wp + 3*HALF + f*4);
    float4 bb = *(const float4*)(bo + (f & 127)*4);
    float4 o;
    o.x = a.x + b.x + c.x + d.x + bb.x;
    o.y = a.y + b.y + c.y + d.y + bb.y;
    o.z = a.z + b.z + c.z + d.z + bb.z;
    o.w = a.w + b.w + c.w + d.w + bb.w;
    *(float4*)(out + f*4) = o;
}

// ---------------------------------------------------------------------------
// Attention v2 (R8, best measured) — fused streaming softmax, no max-sub.
// ---------------------------------------------------------------------------
__global__ __launch_bounds__(256, 2) void attn_kernel(
    const float* __restrict__ qp, const float* __restrict__ kp,
    const float* __restrict__ V,  const float* __restrict__ av,
    float* __restrict__ out) {
    __shared__ float sk[64*68];     // K tile
    __shared__ float sv[64*68];     // V tile
    __shared__ float sp[32*65];     // P tile
    __shared__ float s_av[64];
    __shared__ float s_part[8*32];
    __shared__ float s_inv[32];

    int t    = threadIdx.x;         // 256
    int lane = t & 31;
    int wid  = t >> 5;
    int i0   = blockIdx.x * 32;
    int bh   = blockIdx.y;
    int b    = bh >> 3, h = bh & 7;
    const int h64 = h * 64;
    const int rowbase = b * SEQ;

    if (t < 64) s_av[t] = av[t];

    float q_r[64];
    {
        const float* qrow = qp + (rowbase + i0 + lane) * DMODEL + h64;
#pragma unroll
        for (int d = 0; d < 64; d += 4) {
            float4 v4 = *(const float4*)(qrow + d);
            q_r[d] = v4.x; q_r[d+1] = v4.y; q_r[d+2] = v4.z; q_r[d+3] = v4.w;
        }
    }

    int dt = t & 15, ig = t >> 4;
    int d4 = dt << 2;
    int ia = ig << 1;
    float acc0[4] = {0.f, 0.f, 0.f, 0.f};
    float acc1[4] = {0.f, 0.f, 0.f, 0.f};
    float psum = 0.f;

    int frow = t >> 2;
    int fc16 = (t & 3) << 4;

    __syncthreads();

    for (int jt = 0; jt < SEQ; jt += 64) {
        {
            const float* ks = kp + (rowbase + jt + frow) * DMODEL + h64 + fc16;
            const float* vs = V  + (rowbase + jt + frow) * DMODEL + h64 + fc16;
            float4 k0 = *(const float4*)(ks + 0);
            float4 k1 = *(const float4*)(ks + 4);
            float4 k2 = *(const float4*)(ks + 8);
            float4 k3 = *(const float4*)(ks + 12);
            float4 v0 = *(const float4*)(vs + 0);
            float4 v1 = *(const float4*)(vs + 4);
            float4 v2 = *(const float4*)(vs + 8);
            float4 v3 = *(const float4*)(vs + 12);
            float* dk = &sk[frow*68 + fc16];
            float* dv = &sv[frow*68 + fc16];
            *(float4*)(dk + 0)  = k0;
            *(float4*)(dk + 4)  = k1;
            *(float4*)(dk + 8)  = k2;
            *(float4*)(dk + 12) = k3;
            *(float4*)(dv + 0)  = v0;
            *(float4*)(dv + 4)  = v1;
            *(float4*)(dv + 8)  = v2;
            *(float4*)(dv + 12) = v3;
        }
        __syncthreads();

#pragma unroll
        for (int jj = 0; jj < 8; jj++) {
            int j = wid * 8 + jj;
            const float* krow = &sk[j*68];
            float s = 0.f;
#pragma unroll
            for (int d = 0; d < 64; d += 4) {
                float4 k4 = *(const float4*)(krow + d);
                float4 a4 = *(const float4*)(&s_av[d]);
                s += a4.x * tanh_fast(q_r[d+0] + k4.x);
                s += a4.y * tanh_fast(q_r[d+1] + k4.y);
                s += a4.z * tanh_fast(q_r[d+2] + k4.z);
                s += a4.w * tanh_fast(q_r[d+3] + k4.w);
            }
            float p = __expf(s);
            sp[lane*65 + j] = p;
            psum += p;
        }
        __syncthreads();

        const float* p0 = &sp[ia*65];
        const float* p1 = &sp[(ia+1)*65];
#pragma unroll 8
        for (int j = 0; j < 64; j++) {
            float4 v = *(const float4*)&sv[j*68 + d4];
            float pa = p0[j];
            float pb = p1[j];
            acc0[0] += pa * v.x; acc0[1] += pa * v.y;
            acc0[2] += pa * v.z; acc0[3] += pa * v.w;
            acc1[0] += pb * v.x; acc1[1] += pb * v.y;
            acc1[2] += pb * v.z; acc1[3] += pb * v.w;
        }
        __syncthreads();
    }

    s_part[wid*32 + lane] = psum;
    __syncthreads();
    if (t < 32) {
        float ssum = 0.f;
#pragma unroll
        for (int w = 0; w < 8; w++) ssum += s_part[w*32 + t];
        s_inv[t] = 1.f / ssum;
    }
    __syncthreads();

    float s0 = s_inv[ia], s1 = s_inv[ia+1];
    float4 o0, o1;
    o0.x = acc0[0]*s0; o0.y = acc0[1]*s0; o0.z = acc0[2]*s0; o0.w = acc0[3]*s0;
    o1.x = acc1[0]*s1; o1.y = acc1[1]*s1; o1.z = acc1[2]*s1; o1.w = acc1[3]*s1;
    *(float4*)&out[(rowbase + i0 + ia    ) * DMODEL + h64 + d4] = o0;
    *(float4*)&out[(rowbase + i0 + ia + 1) * DMODEL + h64 + d4] = o1;
}

// ---------------------------------------------------------------------------
extern "C" void kernel_launch(void* const* d_in, const int* in_sizes, int n_in,
                              void* d_out, int out_size) {
    const float* query = (const float*)d_in[0];
    const float* key   = (const float*)d_in[1];
    const float* value = (const float*)d_in[2];
    const float* Wq    = (const float*)d_in[3];
    const float* bq    = (const float*)d_in[4];
    const float* Wk    = (const float*)d_in[5];
    const float* bk    = (const float*)d_in[6];
    const float* Wv    = (const float*)d_in[7];
    const float* bv    = (const float*)d_in[8];
    const float* Wo    = (const float*)d_in[9];
    const float* bo    = (const float*)d_in[10];
    const float* Aq    = (const float*)d_in[11];
    const float* Ak    = (const float*)d_in[12];
    const float* av    = (const float*)d_in[13];
    float* out = (float*)d_out;

    float *pWqE, *pWkE, *pbqE, *pbkE, *pqp, *pkp, *pV, *patt, *pwp;
    cudaGetSymbolAddress((void**)&pWqE, g_WqE);
    cudaGetSymbolAddress((void**)&pWkE, g_WkE);
    cudaGetSymbolAddress((void**)&pbqE, g_bqE);
    cudaGetSymbolAddress((void**)&pbkE, g_bkE);
    cudaGetSymbolAddress((void**)&pqp,  g_qp);
    cudaGetSymbolAddress((void**)&pkp,  g_kp);
    cudaGetSymbolAddress((void**)&pV,   g_V);
    cudaGetSymbolAddress((void**)&patt, g_att);
    cudaGetSymbolAddress((void**)&pwp,  g_wp);

    // prep: effective Q/K weights + biases
    prep_eff<<<dim3(8, 8, 2), 256>>>(Wq, Aq, Wk, Ak, bq, bk);

    // Q/K/V projection GEMMs (TF32 tensor cores), bias epilogue -> 192 CTAs
    gemm_tf32<<<dim3(8, 8, 3), 256>>>(query, pWqE, 0, pbqE, pqp,
                                      key,   pWkE, 0, pbkE, pkp,
                                      value, Wv,   1, bv,   pV,
                                      1, 512);

    // attention (best measured config) -> 256 CTAs
    attn_kernel<<<dim3(SEQ/32, BATCH*NHEADS), 256>>>(pqp, pkp, pV, av, patt);

    // output projection (TF32), split-K x4 -> 256 CTAs
    gemm_tf32<<<dim3(8, 8, 4), 256>>>(patt, Wo, 1, nullptr, pwp,
                                      patt, Wo, 1, nullptr, pwp,
                                      patt, Wo, 1, nullptr, pwp,
                                      4, 128);
    reduce_out<<<(HALF/4)/256, 256>>>(out, bo);
}